// round 16
// baseline (speedup 1.0000x reference)
#include <cuda_runtime.h>
#include <cstdint>

#define S_LEN 2048
#define BATCH 2
#define HEADS 16
#define DDIM  128
#define BM    128
#define BN    64
#define NTILES (S_LEN/BN)
#define ROWSTRIDE (BATCH*HEADS*DDIM)

// ---- smem byte offsets (fp16 buffers, 256B per row of 128 elems) ----
#define QH_OFF 0
#define STG_OFF 32768
#define STG_BYTES 32768
#define KH_O 0
#define VH_O 16384
#define SMEM_TOTAL (STG_OFF + 2*STG_BYTES)   // 98304

__device__ uint16_t g_kh[(size_t)BATCH * HEADS * S_LEN * DDIM];   // 16 MB, [b,h,s,d] fp16 bits
__device__ uint16_t g_vh[(size_t)BATCH * HEADS * S_LEN * DDIM];   // 16 MB, [b,h,s,d] fp16 bits
// fp16 {0,1} mask multipliers, fragment layout: ((b*2048+row)*32 + tile)*32 + qc*8 + j
__device__ uint32_t g_maskf[(size_t)BATCH * S_LEN * 32 * 32];     // 16 MB

// ============ helpers ============
__device__ __forceinline__ uint32_t smem_u32(const void* p) {
    uint32_t a;
    asm("{ .reg .u64 t; cvta.to.shared.u64 t, %1; cvt.u32.u64 %0, t; }" : "=r"(a) : "l"(p));
    return a;
}
__device__ __forceinline__ float ex2f(float x) {
    float r; asm("ex2.approx.f32 %0, %1;" : "=f"(r) : "f"(x)); return r;
}
// pack (first, second) -> fp16x2 word, first in low half
__device__ __forceinline__ uint32_t packhf(float e, float o) {
    uint32_t w; asm("cvt.rn.f16x2.f32 %0, %1, %2;" : "=r"(w) : "f"(o), "f"(e)); return w;
}
__device__ __forceinline__ uint32_t hmul2(uint32_t a, uint32_t b) {
    uint32_t r; asm("mul.rn.f16x2 %0, %1, %2;" : "=r"(r) : "r"(a), "r"(b)); return r;
}

__device__ __forceinline__ void mma_f16(float* c, const uint32_t* a, uint32_t b0, uint32_t b1) {
    asm volatile("mma.sync.aligned.m16n8k16.row.col.f32.f16.f16.f32 "
        "{%0,%1,%2,%3}, {%4,%5,%6,%7}, {%8,%9}, {%0,%1,%2,%3};"
        : "+f"(c[0]), "+f"(c[1]), "+f"(c[2]), "+f"(c[3])
        : "r"(a[0]), "r"(a[1]), "r"(a[2]), "r"(a[3]), "r"(b0), "r"(b1));
}
__device__ __forceinline__ void ldm_x4(uint32_t* r, uint32_t addr) {
    asm volatile("ldmatrix.sync.aligned.m8n8.x4.shared.b16 {%0,%1,%2,%3}, [%4];"
        : "=r"(r[0]), "=r"(r[1]), "=r"(r[2]), "=r"(r[3]) : "r"(addr));
}
// immediate-offset variants: offset folded into the LDSM instruction
#define LDMI(r, base, IMM) \
    asm volatile("ldmatrix.sync.aligned.m8n8.x4.shared.b16 {%0,%1,%2,%3}, [%4+" #IMM "];" \
        : "=r"((r)[0]), "=r"((r)[1]), "=r"((r)[2]), "=r"((r)[3]) : "r"(base))
#define LDMTI(r, base, IMM) \
    asm volatile("ldmatrix.sync.aligned.m8n8.x4.trans.shared.b16 {%0,%1,%2,%3}, [%4+" #IMM "];" \
        : "=r"((r)[0]), "=r"((r)[1]), "=r"((r)[2]), "=r"((r)[3]) : "r"(base))

// STS address for (row r, float4-group c4 in 0..31): 8-byte granularity
__device__ __forceinline__ uint32_t sts_a(int r, int c4) {
    return (uint32_t)((r << 8) + ((((c4 >> 1) ^ (r & 7)) & 15) << 4) + ((c4 & 1) << 3));
}
// byte addr of 16B chunk (row r, chunk c in 0..15) with xor swizzle
__device__ __forceinline__ uint32_t swa(int r, int c) {
    return (uint32_t)((r << 8) + (((c ^ (r & 7)) & 15) << 4));
}
__device__ __forceinline__ void cpa16(uint32_t saddr, const void* g) {
    asm volatile("cp.async.cg.shared.global [%0], [%1], 16;" :: "r"(saddr), "l"(g));
}
__device__ __forceinline__ void cpa_commit() {
    asm volatile("cp.async.commit_group;" ::: "memory");
}

// ============ fused pre-pass: K,V -> fp16 [b,h,s,d]; mask -> fp16 multipliers ============
__global__ void prep_kernel(const float* __restrict__ K, const float* __restrict__ V,
                            const int* __restrict__ mask) {
    int idx = blockIdx.x * 256 + threadIdx.x;       // 0 .. 2097151
    {
        int d4 = idx & 31;
        int h  = (idx >> 5) & 15;
        int b  = (idx >> 9) & 1;
        int s  = idx >> 10;
        size_t in  = (((size_t)s * BATCH + b) * HEADS + h) * DDIM + d4 * 4;
        size_t out = (((size_t)b * HEADS + h) * S_LEN + s) * DDIM + d4 * 4;
        float4 fk = *(const float4*)(K + in);
        float4 fv = *(const float4*)(V + in);
        *(uint2*)(g_kh + out) = make_uint2(packhf(fk.x, fk.y), packhf(fk.z, fk.w));
        *(uint2*)(g_vh + out) = make_uint2(packhf(fv.x, fv.y), packhf(fv.z, fv.w));
    }
    // mask multipliers: 2 words per thread, word w = ((b*2048+row)*32 + i)*32 + qc*8 + j
    #pragma unroll
    for (int t = 0; t < 2; t++) {
        int w   = idx * 2 + t;                      // 0 .. 4194303
        int j   = w & 7;
        int qc  = (w >> 3) & 3;
        int i   = (w >> 5) & 31;
        int row = (w >> 10) & 2047;
        int b   = w >> 21;
        int col = i * 64 + j * 8 + qc * 2;
        int2 m2 = *(const int2*)(mask + ((size_t)b * S_LEN + row) * S_LEN + col);
        g_maskf[w] = (m2.x ? 0u : 0x3C00u) | (m2.y ? 0u : 0x3C000000u);
    }
}

// ============ main kernel ============
__global__ __launch_bounds__(256, 2)
void attn_hmma(const float* __restrict__ Q, float* __restrict__ out)
{
    extern __shared__ __align__(256) char smem[];
    const uint32_t sb = smem_u32(smem);
    const int tid = threadIdx.x, lane = tid & 31, wid = tid >> 5;
    const int bh = blockIdx.y, b = bh >> 4, h = bh & 15;
    const int qbase = blockIdx.x * BM;
    const float scale = 1.4426950408889634f / 11.313708498984761f; // log2e/sqrt(128)

    const int lr16 = lane & 15;     // ldmatrix row-within-16
    const int lc   = lane >> 4;     // ldmatrix chunk select
    const int rq   = lane >> 2;     // row within m8 of C frag
    const int qc   = lane & 3;      // col quad

    // ---- Q: load, scale, fp16 convert, STS ----
    {
        const int tr = tid >> 5, c4 = tid & 31;
        const float* qp = Q + (((size_t)(qbase + tr) * BATCH + b) * HEADS + h) * DDIM + c4 * 4;
        const uint32_t qsts = QH_OFF + sts_a(tr, c4);
        #pragma unroll
        for (int u = 0; u < 16; u++) {
            float4 f = *(const float4*)(qp + (size_t)u * 8 * ROWSTRIDE);
            f.x *= scale; f.y *= scale; f.z *= scale; f.w *= scale;
            uint32_t h0 = packhf(f.x, f.y), h1 = packhf(f.z, f.w);
            *(uint64_t*)(smem + qsts + u * 2048) = (uint64_t)h0 | ((uint64_t)h1 << 32);
        }
    }

    // ---- cp.async tile copy: 4 chunks K + 4 chunks V per thread ----
    const char* khbase = (const char*)(g_kh + (size_t)bh * S_LEN * DDIM);
    const char* vhbase = (const char*)(g_vh + (size_t)bh * S_LEN * DDIM);
    uint32_t csw[4];
    #pragma unroll
    for (int u = 0; u < 4; u++) {
        int chunk = u * 256 + tid;
        csw[u] = swa(chunk >> 4, chunk & 15);
    }

    // prologue: issue tiles 0 and 1
    #pragma unroll
    for (int t = 0; t < 2; t++) {
        const uint32_t stg = sb + STG_OFF + t * STG_BYTES;
        const char* kt = khbase + (size_t)t * BN * DDIM * 2;
        const char* vt = vhbase + (size_t)t * BN * DDIM * 2;
        #pragma unroll
        for (int u = 0; u < 4; u++) {
            int chunk = u * 256 + tid;
            cpa16(stg + KH_O + csw[u], kt + chunk * 16);
            cpa16(stg + VH_O + csw[u], vt + chunk * 16);
        }
        cpa_commit();
    }

    // ---- precomputed Q fragment addresses (kernel-invariant) ----
    const int s7 = lr16 & 7;
    const int arow = wid * 16 + lr16;
    uint32_t qa[8];
    #pragma unroll
    for (int k = 0; k < 8; k++)
        qa[k] = sb + QH_OFF + arow * 256 + (uint32_t)((((2 * k + lc) ^ s7) & 15) << 4);

    // ones-column B fragment for l-sum MMA (col 0 of n8 -> lanes 0..3)
    const uint32_t bones = (lane < 4) ? 0x3C003C00u : 0u;

    // per-thread persistent state
    float o[16][4];
    #pragma unroll
    for (int j = 0; j < 16; j++) { o[j][0] = o[j][1] = o[j][2] = o[j][3] = 0.0f; }
    float lf[4] = {0.0f, 0.0f, 0.0f, 0.0f};

    const int qrow0 = qbase + wid * 16 + rq;
    const uint32_t* mfp = g_maskf + ((size_t)(b * S_LEN + qrow0) * 32) * 32 + qc * 8;

    for (int i = 0; i < NTILES; i++) {
        const uint32_t cur = sb + STG_OFF + (uint32_t)(i & 1) * STG_BYTES;

        // mask multiplier words: 4x LDG.128, independent of smem -> before the wait
        uint32_t mw0[8], mw1[8];
        *(uint4*)(mw0)     = *(const uint4*)(mfp);
        *(uint4*)(mw0 + 4) = *(const uint4*)(mfp + 4);
        *(uint4*)(mw1)     = *(const uint4*)(mfp + 8192);
        *(uint4*)(mw1 + 4) = *(const uint4*)(mfp + 8192 + 4);
        mfp += 32;

        // stage fragment bases for this tile
        uint32_t kb[8];
        {
            const uint32_t delta = cur + (uint32_t)(lr16 * 256) - (sb + QH_OFF + arow * 256);
            #pragma unroll
            for (int t = 0; t < 8; t++) kb[t] = qa[t] + delta;
        }

        if (i == NTILES - 1) asm volatile("cp.async.wait_group 0;" ::: "memory");
        else                 asm volatile("cp.async.wait_group 1;" ::: "memory");
        __syncthreads();

        // ---- GEMM1: S[16x64] = Q K^T ----
        float s[8][4];
        #pragma unroll
        for (int j = 0; j < 8; j++) { s[j][0] = s[j][1] = s[j][2] = s[j][3] = 0.0f; }
        #pragma unroll
        for (int k = 0; k < 8; k++) {
            uint32_t ah[4], bhf[4];
            ldm_x4(ah, qa[k]);
            LDMI(bhf, kb[k], 0);
            mma_f16(s[0], ah, bhf[0], bhf[2]);
            mma_f16(s[1], ah, bhf[1], bhf[3]);
            LDMI(bhf, kb[k], 4096);
            mma_f16(s[2], ah, bhf[0], bhf[2]);
            mma_f16(s[3], ah, bhf[1], bhf[3]);
            LDMI(bhf, kb[k], 8192);
            mma_f16(s[4], ah, bhf[0], bhf[2]);
            mma_f16(s[5], ah, bhf[1], bhf[3]);
            LDMI(bhf, kb[k], 12288);
            mma_f16(s[6], ah, bhf[0], bhf[2]);
            mma_f16(s[7], ah, bhf[1], bhf[3]);
        }

        // ---- softmax: unconditional ex2, pack, fp16 mask multiply (no ALU chains) ----
        uint32_t ph[8][2];
        #pragma unroll
        for (int j = 0; j < 8; j++) {
            float p0 = ex2f(s[j][0]), p1 = ex2f(s[j][1]);
            float p2 = ex2f(s[j][2]), p3 = ex2f(s[j][3]);
            ph[j][0] = hmul2(packhf(p0, p1), mw0[j]);
            ph[j][1] = hmul2(packhf(p2, p3), mw1[j]);
        }

        // ---- GEMM2: O += P V, plus l-sum via ones-column MMA ----
        #pragma unroll
        for (int kt = 0; kt < 4; kt++) {
            uint32_t Ah[4] = { ph[2 * kt][0], ph[2 * kt][1],
                               ph[2 * kt + 1][0], ph[2 * kt + 1][1] };
            mma_f16(lf, Ah, bones, bones);      // row sums -> col 0
            #pragma unroll
            for (int dj = 0; dj < 8; dj++) {
                uint32_t vh[4];
                if      (kt == 0) LDMTI(vh, kb[dj], 16384);
                else if (kt == 1) LDMTI(vh, kb[dj], 20480);
                else if (kt == 2) LDMTI(vh, kb[dj], 24576);
                else              LDMTI(vh, kb[dj], 28672);
                mma_f16(o[2 * dj],     Ah, vh[0], vh[1]);
                mma_f16(o[2 * dj + 1], Ah, vh[2], vh[3]);
            }
        }

        // all warps done with stage (i&1); refill it with tile i+2
        __syncthreads();
        if (i + 2 < NTILES) {
            const char* kt = khbase + (size_t)(i + 2) * BN * DDIM * 2;
            const char* vt = vhbase + (size_t)(i + 2) * BN * DDIM * 2;
            #pragma unroll
            for (int u = 0; u < 4; u++) {
                int chunk = u * 256 + tid;
                cpa16(cur + KH_O + csw[u], kt + chunk * 16);
                cpa16(cur + VH_O + csw[u], vt + chunk * 16);
            }
            cpa_commit();
        }
    }

    // ---- epilogue: l lives in col 0 of lf on qc==0 lanes ----
    const float l0 = __shfl_sync(0xffffffffu, lf[0], lane & 28);
    const float l1 = __shfl_sync(0xffffffffu, lf[2], lane & 28);
    const float inv0 = 1.0f / l0;
    const float inv1 = 1.0f / l1;
    float* op0 = out + (((size_t)qrow0 * BATCH + b) * HEADS + h) * DDIM;
    float* op1 = op0 + (size_t)8 * ROWSTRIDE;
    #pragma unroll
    for (int j = 0; j < 16; j++) {
        int col = j * 8 + qc * 2;
        *(float2*)(op0 + col) = make_float2(o[j][0] * inv0, o[j][1] * inv0);
        *(float2*)(op1 + col) = make_float2(o[j][2] * inv1, o[j][3] * inv1);
    }
}

extern "C" void kernel_launch(void* const* d_in, const int* in_sizes, int n_in,
                              void* d_out, int out_size)
{
    const float* Q = (const float*)d_in[0];
    const float* K = (const float*)d_in[1];
    const float* V = (const float*)d_in[2];
    const int* mask = (const int*)d_in[3];
    float* O = (float*)d_out;

    prep_kernel<<<8192, 256>>>(K, V, mask);

    cudaFuncSetAttribute(attn_hmma, cudaFuncAttributeMaxDynamicSharedMemorySize, SMEM_TOTAL);
    dim3 grid(S_LEN / BM, BATCH * HEADS);
    attn_hmma<<<grid, 256, SMEM_TOTAL>>>(Q, O);
}

// round 17
// speedup vs baseline: 1.1485x; 1.1485x over previous
#include <cuda_runtime.h>
#include <cstdint>

#define S_LEN 2048
#define BATCH 2
#define HEADS 16
#define DDIM  128
#define BM    128
#define BN    64
#define NTILES (S_LEN/BN)
#define ROWSTRIDE (BATCH*HEADS*DDIM)

// ---- smem byte offsets (fp16 buffers, 256B per row of 128 elems) ----
#define QH_OFF 0
#define STG_OFF 32768
#define STG_BYTES 32768
#define KH_O 0
#define VH_O 16384
#define SMEM_TOTAL (STG_OFF + 2*STG_BYTES)   // 98304

__device__ uint64_t g_maskbits[(size_t)BATCH * S_LEN * (S_LEN/64)];        // 1 MB
__device__ uint16_t g_kh[(size_t)BATCH * HEADS * S_LEN * DDIM];            // 16 MB, [b,h,s,d] fp16 bits
__device__ uint16_t g_vh[(size_t)BATCH * HEADS * S_LEN * DDIM];            // 16 MB, [b,h,s,d] fp16 bits

// ============ helpers ============
__device__ __forceinline__ uint32_t smem_u32(const void* p) {
    uint32_t a;
    asm("{ .reg .u64 t; cvta.to.shared.u64 t, %1; cvt.u32.u64 %0, t; }" : "=r"(a) : "l"(p));
    return a;
}
__device__ __forceinline__ float ex2f(float x) {
    float r; asm("ex2.approx.f32 %0, %1;" : "=f"(r) : "f"(x)); return r;
}
// pack (first, second) -> fp16x2 word, first in low half
__device__ __forceinline__ uint32_t packhf(float e, float o) {
    uint32_t w; asm("cvt.rn.f16x2.f32 %0, %1, %2;" : "=r"(w) : "f"(o), "f"(e)); return w;
}
__device__ __forceinline__ uint32_t hmul2(uint32_t a, uint32_t b) {
    uint32_t r; asm("mul.rn.f16x2 %0, %1, %2;" : "=r"(r) : "r"(a), "r"(b)); return r;
}

__device__ __forceinline__ void mma_f16(float* c, const uint32_t* a, uint32_t b0, uint32_t b1) {
    asm volatile("mma.sync.aligned.m16n8k16.row.col.f32.f16.f16.f32 "
        "{%0,%1,%2,%3}, {%4,%5,%6,%7}, {%8,%9}, {%0,%1,%2,%3};"
        : "+f"(c[0]), "+f"(c[1]), "+f"(c[2]), "+f"(c[3])
        : "r"(a[0]), "r"(a[1]), "r"(a[2]), "r"(a[3]), "r"(b0), "r"(b1));
}
__device__ __forceinline__ void ldm_x4(uint32_t* r, uint32_t addr) {
    asm volatile("ldmatrix.sync.aligned.m8n8.x4.shared.b16 {%0,%1,%2,%3}, [%4];"
        : "=r"(r[0]), "=r"(r[1]), "=r"(r[2]), "=r"(r[3]) : "r"(addr));
}
__device__ __forceinline__ void ldm_x4_t(uint32_t* r, uint32_t addr) {
    asm volatile("ldmatrix.sync.aligned.m8n8.x4.trans.shared.b16 {%0,%1,%2,%3}, [%4];"
        : "=r"(r[0]), "=r"(r[1]), "=r"(r[2]), "=r"(r[3]) : "r"(addr));
}
// byte addr of 16B chunk (row r, chunk c in 0..15) with xor swizzle
__device__ __forceinline__ uint32_t swa(int r, int c) {
    return (uint32_t)((r << 8) + (((c ^ (r & 7)) & 15) << 4));
}
// STS address for (row r, float4-group c4 in 0..31): 8-byte granularity
__device__ __forceinline__ uint32_t sts_a(int r, int c4) {
    return (uint32_t)((r << 8) + ((((c4 >> 1) ^ (r & 7)) & 15) << 4) + ((c4 & 1) << 3));
}
__device__ __forceinline__ void cpa16(uint32_t saddr, const void* g) {
    asm volatile("cp.async.cg.shared.global [%0], [%1], 16;" :: "r"(saddr), "l"(g));
}
__device__ __forceinline__ void cpa_commit() {
    asm volatile("cp.async.commit_group;" ::: "memory");
}

// ============ fused pre-pass: convert K,V to fp16 [b,h,s,d] + pack mask bitmap ============
__global__ void prep_kernel(const float* __restrict__ K, const float* __restrict__ V,
                            const int* __restrict__ mask) {
    int idx = blockIdx.x * 256 + threadIdx.x;       // 0 .. 2097151  (float4 groups)
    {
        int d4 = idx & 31;
        int h  = (idx >> 5) & 15;
        int b  = (idx >> 9) & 1;
        int s  = idx >> 10;
        size_t in  = (((size_t)s * BATCH + b) * HEADS + h) * DDIM + d4 * 4;
        size_t out = (((size_t)b * HEADS + h) * S_LEN + s) * DDIM + d4 * 4;
        float4 fk = *(const float4*)(K + in);
        float4 fv = *(const float4*)(V + in);
        *(uint2*)(g_kh + out) = make_uint2(packhf(fk.x, fk.y), packhf(fk.z, fk.w));
        *(uint2*)(g_vh + out) = make_uint2(packhf(fv.x, fv.y), packhf(fv.z, fv.w));
    }
    if (idx < BATCH * S_LEN * 32) {                 // 131072 mask words
        int w   = idx & 31;
        int row = (idx >> 5) & (S_LEN - 1);
        int b   = idx >> 16;
        const int4* mp = (const int4*)(mask + ((size_t)b * S_LEN + row) * S_LEN + w * 64);
        uint64_t bits = 0;
        #pragma unroll
        for (int u = 0; u < 16; u++) {
            int4 m = mp[u];
            bits |= (uint64_t)(m.x != 0) << (4 * u)
                 |  (uint64_t)(m.y != 0) << (4 * u + 1)
                 |  (uint64_t)(m.z != 0) << (4 * u + 2)
                 |  (uint64_t)(m.w != 0) << (4 * u + 3);
        }
        g_maskbits[idx] = bits;
    }
}

// ============ main kernel ============
__global__ __launch_bounds__(256, 2)
void attn_hmma(const float* __restrict__ Q, float* __restrict__ out)
{
    extern __shared__ __align__(256) char smem[];
    const uint32_t sb = smem_u32(smem);
    const int tid = threadIdx.x, lane = tid & 31, wid = tid >> 5;
    const int bh = blockIdx.y, b = bh >> 4, h = bh & 15;
    const int qbase = blockIdx.x * BM;
    const float scale = 1.4426950408889634f / 11.313708498984761f; // log2e/sqrt(128)

    const int lr16 = lane & 15;     // ldmatrix row-within-16
    const int lc   = lane >> 4;     // ldmatrix chunk select
    const int rq   = lane >> 2;     // row within m8 of C frag
    const int qc   = lane & 3;      // col quad

    // ---- Q: load, scale, fp16 convert, STS ----
    {
        const int tr = tid >> 5, c4 = tid & 31;
        const float* qp = Q + (((size_t)(qbase + tr) * BATCH + b) * HEADS + h) * DDIM + c4 * 4;
        const uint32_t qsts = QH_OFF + sts_a(tr, c4);
        #pragma unroll
        for (int u = 0; u < 16; u++) {
            float4 f = *(const float4*)(qp + (size_t)u * 8 * ROWSTRIDE);
            f.x *= scale; f.y *= scale; f.z *= scale; f.w *= scale;
            uint32_t h0 = packhf(f.x, f.y), h1 = packhf(f.z, f.w);
            *(uint64_t*)(smem + qsts + u * 2048) = (uint64_t)h0 | ((uint64_t)h1 << 32);
        }
    }

    // ---- cp.async tile copy: 4 chunks K + 4 chunks V per thread ----
    const char* khbase = (const char*)(g_kh + (size_t)bh * S_LEN * DDIM);
    const char* vhbase = (const char*)(g_vh + (size_t)bh * S_LEN * DDIM);
    uint32_t csw[4];       // swizzled smem offsets of this thread's 4 chunks
    #pragma unroll
    for (int u = 0; u < 4; u++) {
        int chunk = u * 256 + tid;
        csw[u] = swa(chunk >> 4, chunk & 15);
    }

    // prologue: issue tiles 0 and 1
    #pragma unroll
    for (int t = 0; t < 2; t++) {
        const uint32_t stg = sb + STG_OFF + t * STG_BYTES;
        const char* kt = khbase + (size_t)t * BN * DDIM * 2;
        const char* vt = vhbase + (size_t)t * BN * DDIM * 2;
        #pragma unroll
        for (int u = 0; u < 4; u++) {
            int chunk = u * 256 + tid;
            cpa16(stg + KH_O + csw[u], kt + chunk * 16);
            cpa16(stg + VH_O + csw[u], vt + chunk * 16);
        }
        cpa_commit();
    }

    // ones-column B fragment for l-sum MMA (col 0 of n8 -> lanes 0..3)
    const uint32_t bones = (lane < 4) ? 0x3C003C00u : 0u;

    // per-thread persistent state
    float o[16][4];
    #pragma unroll
    for (int j = 0; j < 16; j++) { o[j][0] = o[j][1] = o[j][2] = o[j][3] = 0.0f; }
    float lf[4] = {0.0f, 0.0f, 0.0f, 0.0f};

    const int qrow0 = qbase + wid * 16 + rq;
    const uint64_t* mp = g_maskbits + ((size_t)b * S_LEN + qrow0) * 32;

    const uint32_t qh_base = sb + QH_OFF;
    const int arow = wid * 16 + lr16;

    for (int i = 0; i < NTILES; i++) {
        const uint32_t cur = sb + STG_OFF + (uint32_t)(i & 1) * STG_BYTES;

        // mask words: independent of smem, load before the wait; pre-shift by qc
        uint64_t m0 = mp[0] >> (qc * 2);
        uint64_t m1 = mp[256] >> (qc * 2);     // +8 rows * 32 words
        mp++;

        // wait for tile i's copies, then make visible to all warps
        if (i == NTILES - 1) asm volatile("cp.async.wait_group 0;" ::: "memory");
        else                 asm volatile("cp.async.wait_group 1;" ::: "memory");
        __syncthreads();

        // ---- GEMM1: S[16x64] = Q K^T ----
        float s[8][4];
        #pragma unroll
        for (int j = 0; j < 8; j++) { s[j][0] = s[j][1] = s[j][2] = s[j][3] = 0.0f; }
        #pragma unroll
        for (int k = 0; k < 8; k++) {
            uint32_t ah[4];
            ldm_x4(ah, qh_base + swa(arow, 2 * k + lc));
            #pragma unroll
            for (int jj = 0; jj < 4; jj++) {
                uint32_t bhf[4];
                ldm_x4(bhf, cur + KH_O + swa(jj * 16 + lr16, 2 * k + lc));
                mma_f16(s[2 * jj],     ah, bhf[0], bhf[2]);
                mma_f16(s[2 * jj + 1], ah, bhf[1], bhf[3]);
            }
        }

        // ---- softmax: ex2, pack, arithmetic fp16 mask multiplier from bitmap ----
        uint32_t ph[8][2];
        #pragma unroll
        for (int j = 0; j < 8; j++) {
            uint32_t t0 = ((uint32_t)(m0 >> (8 * j))) & 3u;
            uint32_t t1 = ((uint32_t)(m1 >> (8 * j))) & 3u;
            uint32_t w0 = 0x3C003C00u - ((t0 & 1u) * 0x3C00u) - ((t0 & 2u) * 0x1E000000u);
            uint32_t w1 = 0x3C003C00u - ((t1 & 1u) * 0x3C00u) - ((t1 & 2u) * 0x1E000000u);
            ph[j][0] = hmul2(packhf(ex2f(s[j][0]), ex2f(s[j][1])), w0);
            ph[j][1] = hmul2(packhf(ex2f(s[j][2]), ex2f(s[j][3])), w1);
        }

        // ---- GEMM2: O += P V, plus l-sum via ones-column MMA ----
        #pragma unroll
        for (int kt = 0; kt < 4; kt++) {
            uint32_t Ah[4] = { ph[2 * kt][0], ph[2 * kt][1],
                               ph[2 * kt + 1][0], ph[2 * kt + 1][1] };
            mma_f16(lf, Ah, bones, bones);      // row sums -> col 0
            #pragma unroll
            for (int dj = 0; dj < 8; dj++) {
                uint32_t vh[4];
                ldm_x4_t(vh, cur + VH_O + swa(kt * 16 + lr16, 2 * dj + lc));
                mma_f16(o[2 * dj],     Ah, vh[0], vh[1]);
                mma_f16(o[2 * dj + 1], Ah, vh[2], vh[3]);
            }
        }

        // all warps done with stage (i&1); refill it with tile i+2
        __syncthreads();
        if (i + 2 < NTILES) {
            const char* kt = khbase + (size_t)(i + 2) * BN * DDIM * 2;
            const char* vt = vhbase + (size_t)(i + 2) * BN * DDIM * 2;
            #pragma unroll
            for (int u = 0; u < 4; u++) {
                int chunk = u * 256 + tid;
                cpa16(cur + KH_O + csw[u], kt + chunk * 16);
                cpa16(cur + VH_O + csw[u], vt + chunk * 16);
            }
            cpa_commit();
        }
    }

    // ---- epilogue: l lives in col 0 of lf on qc==0 lanes ----
    const float l0 = __shfl_sync(0xffffffffu, lf[0], lane & 28);
    const float l1 = __shfl_sync(0xffffffffu, lf[2], lane & 28);
    const float inv0 = 1.0f / l0;
    const float inv1 = 1.0f / l1;
    float* op0 = out + (((size_t)qrow0 * BATCH + b) * HEADS + h) * DDIM;
    float* op1 = op0 + (size_t)8 * ROWSTRIDE;
    #pragma unroll
    for (int j = 0; j < 16; j++) {
        int col = j * 8 + qc * 2;
        *(float2*)(op0 + col) = make_float2(o[j][0] * inv0, o[j][1] * inv0);
        *(float2*)(op1 + col) = make_float2(o[j][2] * inv1, o[j][3] * inv1);
    }
}

extern "C" void kernel_launch(void* const* d_in, const int* in_sizes, int n_in,
                              void* d_out, int out_size)
{
    const float* Q = (const float*)d_in[0];
    const float* K = (const float*)d_in[1];
    const float* V = (const float*)d_in[2];
    const int* mask = (const int*)d_in[3];
    float* O = (float*)d_out;

    prep_kernel<<<8192, 256>>>(K, V, mask);

    cudaFuncSetAttribute(attn_hmma, cudaFuncAttributeMaxDynamicSharedMemorySize, SMEM_TOTAL);
    dim3 grid(S_LEN / BM, BATCH * HEADS);
    attn_hmma<<<grid, 256, SMEM_TOTAL>>>(Q, O);
}